// round 5
// baseline (speedup 1.0000x reference)
#include <cuda_runtime.h>
#include <math.h>

// Problem constants
#define D_CH   2048
#define LSEQ   8192
#define NST    64
#define TCH    64      // chunk length for the scan
#define NCHUNK 128     // LSEQ / TCH

// ---------------- device scratch (static, no allocation) ----------------
__device__ double g_GJ[64 * 128];        // Gauss-Jordan augmented [M | I + d/2 A]
__device__ float  g_dA[64 * 64];         // discretized A (fp32, from fp64 solve)
__device__ float  g_inv[64 * 64];        // M^{-1} = (dA + I)/2
__device__ float  g_dBt[2048 * 64];      // dB transposed: [d][n]
__device__ float  g_Ut[8192 * 64];       // U transposed: [t][n]
__device__ float  g_Ht[8192 * 64];       // H transposed: [t][n]
__device__ float  g_esum[NCHUNK * 64];   // per-chunk local scan result (h0 = 0)
__device__ float  g_hstart[NCHUNK * 64]; // state entering each chunk
__device__ float  g_delta;

// ---------------- 1) fp64 Gauss-Jordan: dA and inv in one solve ----------------
// Solve (I - d/2 A) dA = (I + d/2 A).  M is diagonally dominant (|offdiag row sum|
// << 1), so no pivoting needed and the solve is very well conditioned.
// inv = (dA + I) / 2 exactly (algebraic identity), no second solve needed.
__global__ void prep_kernel(const float* __restrict__ A, const float* __restrict__ logd)
{
    int tid = threadIdx.x;                 // 128 threads
    double delta = exp((double)logd[0]);

    for (int idx = tid; idx < 64 * 128; idx += 128) {
        int i = idx >> 7, j = idx & 127;
        double v;
        if (j < 64) {
            v = (i == j ? 1.0 : 0.0) - 0.5 * delta * (double)A[i * 64 + j];
        } else {
            int jj = j - 64;
            v = (i == jj ? 1.0 : 0.0) + 0.5 * delta * (double)A[i * 64 + jj];
        }
        g_GJ[idx] = v;
    }
    __syncthreads();

    __shared__ double fac[64];
    __shared__ double pivrow[128];

    for (int k = 0; k < 64; k++) {
        double invp = 1.0 / g_GJ[k * 128 + k];
        pivrow[tid] = g_GJ[k * 128 + tid] * invp;
        if (tid < 64) fac[tid] = g_GJ[tid * 128 + k];
        __syncthreads();
        g_GJ[k * 128 + tid] = pivrow[tid];
        for (int idx = tid; idx < 64 * 128; idx += 128) {
            int i = idx >> 7, j = idx & 127;
            if (i != k) g_GJ[idx] -= fac[i] * pivrow[j];
        }
        __syncthreads();
    }

    for (int idx = tid; idx < 64 * 64; idx += 128) {
        int i = idx >> 6, j = idx & 63;
        double da = g_GJ[i * 128 + 64 + j];
        g_dA[idx]  = (float)da;
        g_inv[idx] = (float)(0.5 * (da + (i == j ? 1.0 : 0.0)));
    }
    if (tid == 0) g_delta = (float)delta;
}

// ---------------- 2) dB^T[d][n] = delta * (inv @ B)^T ----------------
__global__ __launch_bounds__(256) void dB_kernel(const float* __restrict__ B)
{
    __shared__ float inv_s[64 * 64];
    int tid = threadIdx.x;
    for (int idx = tid; idx < 4096; idx += 256) inv_s[idx] = g_inv[idx];
    __syncthreads();

    float delta = g_delta;
    int d  = blockIdx.x * 64 + (tid & 63);
    int n0 = (tid >> 6) * 16;

    float acc[16];
#pragma unroll
    for (int q = 0; q < 16; q++) acc[q] = 0.f;

    for (int k = 0; k < 64; k++) {
        float b = B[k * 2048 + d];              // coalesced
#pragma unroll
        for (int q = 0; q < 16; q++) acc[q] += inv_s[(n0 + q) * 64 + k] * b; // broadcast
    }
#pragma unroll
    for (int q = 0; q < 16; q++) g_dBt[d * 64 + n0 + q] = delta * acc[q];
}

// ---------------- 3) GEMM1: Ut[t][n] = (dB @ X)^T  (K = 2048) ----------------
// Grid: 128 blocks, each owns a 64-wide t-tile, all 64 n-rows.
__global__ __launch_bounds__(256) void gemm1_kernel(const float* __restrict__ X)
{
    __shared__ __align__(16) float sB[32 * 64];  // [kk][n]
    __shared__ __align__(16) float sX[32 * 64];  // [kk][t]
    int tid = threadIdx.x;
    int t0  = blockIdx.x * 64;
    int ty  = tid >> 4, tx = tid & 15;           // ty -> n (4 each), tx -> t (4 each)

    float acc[4][4];
#pragma unroll
    for (int r = 0; r < 4; r++)
#pragma unroll
        for (int c = 0; c < 4; c++) acc[r][c] = 0.f;

    for (int d0 = 0; d0 < 2048; d0 += 32) {
        for (int idx = tid; idx < 2048; idx += 256) {
            int kk = idx >> 6, c = idx & 63;
            sB[idx] = g_dBt[(d0 + kk) * 64 + c];
            sX[idx] = X[(d0 + kk) * 8192 + t0 + c];
        }
        __syncthreads();
#pragma unroll 8
        for (int kk = 0; kk < 32; kk++) {
            float4 a4 = *(const float4*)(sB + kk * 64 + ty * 4);
            float4 b4 = *(const float4*)(sX + kk * 64 + tx * 4);
            float av[4] = {a4.x, a4.y, a4.z, a4.w};
            float bv[4] = {b4.x, b4.y, b4.z, b4.w};
#pragma unroll
            for (int r = 0; r < 4; r++)
#pragma unroll
                for (int c = 0; c < 4; c++) acc[r][c] += av[r] * bv[c];
        }
        __syncthreads();
    }
#pragma unroll
    for (int j = 0; j < 4; j++) {
        float4 o;
        o.x = acc[0][j]; o.y = acc[1][j]; o.z = acc[2][j]; o.w = acc[3][j];
        *(float4*)(g_Ut + (t0 + tx * 4 + j) * 64 + ty * 4) = o;
    }
}

// ---------------- 4a) pass A: local scans with h0 = 0, emit chunk sums ----------------
__global__ __launch_bounds__(256) void scan_passA()
{
    __shared__ float h_s[64];
    __shared__ float partial[4][64];
    __shared__ float u_s[64 * 64];
    int tid = threadIdx.x, c = blockIdx.x;
    int part = tid >> 6, i = tid & 63;

    float a[16];
#pragma unroll
    for (int q = 0; q < 16; q++) a[q] = g_dA[i * 64 + part * 16 + q];
    for (int idx = tid; idx < 4096; idx += 256) u_s[idx] = g_Ut[c * 4096 + idx];
    if (tid < 64) h_s[tid] = 0.f;
    __syncthreads();

    for (int j = 0; j < TCH; j++) {
        float acc = 0.f;
#pragma unroll
        for (int q = 0; q < 16; q++) acc += a[q] * h_s[part * 16 + q];  // h broadcast
        partial[part][i] = acc;
        __syncthreads();
        if (tid < 64)
            h_s[tid] = partial[0][tid] + partial[1][tid] + partial[2][tid] + partial[3][tid]
                       + u_s[j * 64 + tid];
        __syncthreads();
    }
    if (tid < 64) g_esum[c * 64 + tid] = h_s[tid];
}

// ---------------- 4b) pass B: dA^64 via squaring + boundary-state combine ----------------
__global__ __launch_bounds__(256) void scan_passB()
{
    __shared__ float buf0[64 * 64];
    __shared__ float buf1[64 * 64];
    __shared__ float h_s[64];
    __shared__ float partial[4][64];
    int tid = threadIdx.x;

    for (int idx = tid; idx < 4096; idx += 256) buf0[idx] = g_dA[idx];
    __syncthreads();

    float* in  = buf0;
    float* out = buf1;
    int ty = tid >> 4, tx = tid & 15;

    for (int s = 0; s < 6; s++) {              // dA^2 ... dA^64
        float acc[4][4];
#pragma unroll
        for (int r = 0; r < 4; r++)
#pragma unroll
            for (int j = 0; j < 4; j++) acc[r][j] = 0.f;
        for (int k = 0; k < 64; k++) {
            float bv[4];
#pragma unroll
            for (int j = 0; j < 4; j++) bv[j] = in[k * 64 + tx * 4 + j];
#pragma unroll
            for (int r = 0; r < 4; r++) {
                float av = in[(ty * 4 + r) * 64 + k];
#pragma unroll
                for (int j = 0; j < 4; j++) acc[r][j] += av * bv[j];
            }
        }
#pragma unroll
        for (int r = 0; r < 4; r++)
#pragma unroll
            for (int j = 0; j < 4; j++)
                out[(ty * 4 + r) * 64 + tx * 4 + j] = acc[r][j];
        __syncthreads();
        float* tmp = in; in = out; out = tmp;
    }

    // combine: hstart[c] = state entering chunk c; h <- dA^64 h + esum[c]
    int part = tid >> 6, i = tid & 63;
    float a[16];
#pragma unroll
    for (int q = 0; q < 16; q++) a[q] = in[i * 64 + part * 16 + q];
    if (tid < 64) h_s[tid] = 0.f;
    __syncthreads();

    for (int c = 0; c < NCHUNK; c++) {
        if (tid < 64) g_hstart[c * 64 + tid] = h_s[tid];
        float acc = 0.f;
#pragma unroll
        for (int q = 0; q < 16; q++) acc += a[q] * h_s[part * 16 + q];
        partial[part][i] = acc;
        __syncthreads();
        if (tid < 64)
            h_s[tid] = partial[0][tid] + partial[1][tid] + partial[2][tid] + partial[3][tid]
                       + g_esum[c * 64 + tid];
        __syncthreads();
    }
}

// ---------------- 4c) pass C: rerun local scans with correct h0, write H ----------------
__global__ __launch_bounds__(256) void scan_passC()
{
    __shared__ float h_s[64];
    __shared__ float partial[4][64];
    __shared__ float u_s[64 * 64];
    int tid = threadIdx.x, c = blockIdx.x;
    int part = tid >> 6, i = tid & 63;

    float a[16];
#pragma unroll
    for (int q = 0; q < 16; q++) a[q] = g_dA[i * 64 + part * 16 + q];
    for (int idx = tid; idx < 4096; idx += 256) u_s[idx] = g_Ut[c * 4096 + idx];
    if (tid < 64) h_s[tid] = g_hstart[c * 64 + tid];
    __syncthreads();

    for (int j = 0; j < TCH; j++) {
        float acc = 0.f;
#pragma unroll
        for (int q = 0; q < 16; q++) acc += a[q] * h_s[part * 16 + q];
        partial[part][i] = acc;
        __syncthreads();
        if (tid < 64) {
            float hn = partial[0][tid] + partial[1][tid] + partial[2][tid] + partial[3][tid]
                       + u_s[j * 64 + tid];
            h_s[tid] = hn;
            g_Ht[c * 4096 + j * 64 + tid] = hn;
        }
        __syncthreads();
    }
}

// ---------------- 5) GEMM2: Y[d][t] = C @ H + Dp * X  (K = 64) ----------------
__global__ __launch_bounds__(256) void gemm2_kernel(const float* __restrict__ X,
                                                    const float* __restrict__ C,
                                                    const float* __restrict__ Dp,
                                                    float* __restrict__ Y)
{
    __shared__ float sCt[64 * 65];   // [n][d], padded
    __shared__ float sHt[64 * 65];   // [n][t], padded
    int tid = threadIdx.x;
    int t0 = blockIdx.x * 64, d0 = blockIdx.y * 64;

    for (int idx = tid; idx < 4096; idx += 256) {
        int r = idx >> 6, c = idx & 63;
        sCt[c * 65 + r] = C[(d0 + r) * 64 + c];        // coalesced read, padded write
        sHt[c * 65 + r] = g_Ht[(t0 + r) * 64 + c];
    }
    __syncthreads();

    int ty = tid >> 4, tx = tid & 15;                  // ty -> d (4), tx -> t (4)
    float acc[4][4];
#pragma unroll
    for (int r = 0; r < 4; r++)
#pragma unroll
        for (int j = 0; j < 4; j++) acc[r][j] = 0.f;

#pragma unroll 8
    for (int k = 0; k < 64; k++) {
        float av[4], bv[4];
#pragma unroll
        for (int r = 0; r < 4; r++) av[r] = sCt[k * 65 + ty * 4 + r];
#pragma unroll
        for (int j = 0; j < 4; j++) bv[j] = sHt[k * 65 + tx * 4 + j];
#pragma unroll
        for (int r = 0; r < 4; r++)
#pragma unroll
            for (int j = 0; j < 4; j++) acc[r][j] += av[r] * bv[j];
    }

#pragma unroll
    for (int r = 0; r < 4; r++) {
        int d = d0 + ty * 4 + r;
        float dp = Dp[d];
        float4 xv = *(const float4*)(X + d * LSEQ + t0 + tx * 4);
        float4 o;
        o.x = acc[r][0] + dp * xv.x;
        o.y = acc[r][1] + dp * xv.y;
        o.z = acc[r][2] + dp * xv.z;
        o.w = acc[r][3] + dp * xv.w;
        *(float4*)(Y + d * LSEQ + t0 + tx * 4) = o;
    }
}

// ---------------- launch ----------------
extern "C" void kernel_launch(void* const* d_in, const int* in_sizes, int n_in,
                              void* d_out, int out_size)
{
    const float* X    = (const float*)d_in[0];   // (2048, 8192)
    const float* A    = (const float*)d_in[1];   // (64, 64)
    const float* B    = (const float*)d_in[2];   // (64, 2048)
    const float* C    = (const float*)d_in[3];   // (2048, 64)
    const float* Dp   = (const float*)d_in[4];   // (2048,)
    const float* logd = (const float*)d_in[5];   // (1,)
    float* Y = (float*)d_out;                    // (2048, 8192)

    prep_kernel<<<1, 128>>>(A, logd);
    dB_kernel<<<32, 256>>>(B);
    gemm1_kernel<<<128, 256>>>(X);
    scan_passA<<<NCHUNK, 256>>>();
    scan_passB<<<1, 256>>>();
    scan_passC<<<NCHUNK, 256>>>();
    dim3 g2(LSEQ / 64, D_CH / 64);
    gemm2_kernel<<<g2, 256>>>(X, C, Dp, Y);
}